// round 13
// baseline (speedup 1.0000x reference)
#include <cuda_runtime.h>

#define NUM_STEPS 20
#define DT_HALF (0.5f * (1.0f / 20.0f))   // DT/2 = (GATE_TIME/NUM_STEPS)/2

#define ROT(a0, a1, b0, b1, vr0, vr1, vi0, vi1)            \
    do {                                                   \
        vr0.x = fmaf(c, a0.x,  s * b1.x);                  \
        vr0.y = fmaf(c, a0.y,  s * b1.y);                  \
        vr0.z = fmaf(c, a0.z,  s * b1.z);                  \
        vr0.w = fmaf(c, a0.w,  s * b1.w);                  \
        vr1.x = fmaf(c, a1.x,  s * b0.x);                  \
        vr1.y = fmaf(c, a1.y,  s * b0.y);                  \
        vr1.z = fmaf(c, a1.z,  s * b0.z);                  \
        vr1.w = fmaf(c, a1.w,  s * b0.w);                  \
        vi0.x = fmaf(c, b0.x, -s * a1.x);                  \
        vi0.y = fmaf(c, b0.y, -s * a1.y);                  \
        vi0.z = fmaf(c, b0.z, -s * a1.z);                  \
        vi0.w = fmaf(c, b0.w, -s * a1.w);                  \
        vi1.x = fmaf(c, b1.x, -s * a0.x);                  \
        vi1.y = fmaf(c, b1.y, -s * a0.y);                  \
        vi1.z = fmaf(c, b1.z, -s * a0.z);                  \
        vi1.w = fmaf(c, b1.w, -s * a0.w);                  \
    } while (0)

__device__ __forceinline__ void get_cs(const float* __restrict__ amps,
                                       float& c, float& s) {
    float th = 0.f;
    #pragma unroll
    for (int k = 0; k < NUM_STEPS; ++k) th += __ldg(&amps[k]);
    th *= DT_HALF;
    sincosf(th, &s, &c);
}

// Exact-fit: 4 float4 per stream per thread, block tile = 1024 float4.
// Plain LDG.128/STG.128, default cache policy (every other variant regressed).
__global__ void __launch_bounds__(256) grape_kernel_x4(
    const float* __restrict__ amps,
    const float4* __restrict__ r0, const float4* __restrict__ r1,
    const float4* __restrict__ i0, const float4* __restrict__ i1,
    float4* __restrict__ or0, float4* __restrict__ or1,
    float4* __restrict__ oi0, float4* __restrict__ oi1)
{
    float c, s;
    get_cs(amps, c, s);

    const int base = blockIdx.x * 1024 + threadIdx.x;

    float4 a0[4], a1[4], b0[4], b1[4];
    #pragma unroll
    for (int j = 0; j < 4; ++j) {
        const int e = base + j * 256;
        a0[j] = r0[e]; a1[j] = r1[e]; b0[j] = i0[e]; b1[j] = i1[e];
    }

    #pragma unroll
    for (int j = 0; j < 4; ++j) {
        const int e = base + j * 256;
        float4 vr0, vr1, vi0, vi1;
        ROT(a0[j], a1[j], b0[j], b1[j], vr0, vr1, vi0, vi1);
        or0[e] = vr0; or1[e] = vr1; oi0[e] = vi0; oi1[e] = vi1;
    }
}

// Guarded fallback (2 float4/thread, any size).
__global__ void __launch_bounds__(256) grape_kernel_guarded(
    const float* __restrict__ amps,
    const float4* __restrict__ r0, const float4* __restrict__ r1,
    const float4* __restrict__ i0, const float4* __restrict__ i1,
    float4* __restrict__ or0, float4* __restrict__ or1,
    float4* __restrict__ oi0, float4* __restrict__ oi1,
    int n4)
{
    float c, s;
    get_cs(amps, c, s);

    #pragma unroll
    for (int j = 0; j < 2; ++j) {
        const int e = blockIdx.x * 512 + j * 256 + threadIdx.x;
        if (e < n4) {
            float4 a0 = r0[e], a1 = r1[e], b0 = i0[e], b1 = i1[e];
            float4 vr0, vr1, vi0, vi1;
            ROT(a0, a1, b0, b1, vr0, vr1, vi0, vi1);
            or0[e] = vr0; or1[e] = vr1; oi0[e] = vi0; oi1[e] = vi1;
        }
    }
}

extern "C" void kernel_launch(void* const* d_in, const int* in_sizes, int n_in,
                              void* d_out, int out_size) {
    const float* amps       = (const float*)d_in[0];   // [20]
    const float* state_real = (const float*)d_in[1];   // [2, B]
    const float* state_imag = (const float*)d_in[2];   // [2, B]
    float* out = (float*)d_out;                        // [2, 2, B]

    const int B  = in_sizes[1] / 2;   // 8388608
    const int n4 = B / 4;             // 2097152 float4 per stream

    const float4* r0 = (const float4*)(state_real);
    const float4* r1 = (const float4*)(state_real + B);
    const float4* i0 = (const float4*)(state_imag);
    const float4* i1 = (const float4*)(state_imag + B);

    float4* or0 = (float4*)(out);
    float4* or1 = (float4*)(out + (size_t)B);
    float4* oi0 = (float4*)(out + 2 * (size_t)B);
    float4* oi1 = (float4*)(out + 3 * (size_t)B);

    if ((B & 3) == 0 && (n4 & 1023) == 0) {
        grape_kernel_x4<<<n4 / 1024, 256>>>(amps, r0, r1, i0, i1,
                                            or0, or1, oi0, oi1);
    } else {
        int blocks = (n4 + 511) / 512;
        grape_kernel_guarded<<<blocks, 256>>>(amps, r0, r1, i0, i1,
                                              or0, or1, oi0, oi1, n4);
    }
}

// round 14
// speedup vs baseline: 1.0007x; 1.0007x over previous
#include <cuda_runtime.h>

#define NUM_STEPS 20
#define DT_HALF (0.5f * (1.0f / 20.0f))   // DT/2 = (GATE_TIME/NUM_STEPS)/2

// FINAL kernel. All 20 rotation steps share the generator X, so they compose
// into ONE rotation by theta = sum(a_k)*DT/2 — applied as a 2x2 complex
// rotation over 8.4M columns. Purely HBM-bound: 256 MB irreducible traffic
// at ~5.9 TB/s effective (74% of spec), the measured mixed r/w ceiling.
// Config locked by measurement: flat grid, 256 thr/block, 2 float4 per stream
// per thread, plain LDG.128/STG.128, default cache policy. Regressions proven:
// __ldcs/__stcs, L2::evict_last (full+half), LDG.256, persistent grids.
__global__ void __launch_bounds__(256) grape_fused_kernel(
    const float* __restrict__ amps,
    const float4* __restrict__ r0, const float4* __restrict__ r1,
    const float4* __restrict__ i0, const float4* __restrict__ i1,
    float4* __restrict__ or0, float4* __restrict__ or1,
    float4* __restrict__ oi0, float4* __restrict__ oi1,
    int n4)
{
    // Uniform angle: per-thread sum of 20 broadcast loads (L1/L2 hits after wave 1).
    float th = 0.f;
    #pragma unroll
    for (int k = 0; k < NUM_STEPS; ++k) th += __ldg(&amps[k]);
    th *= DT_HALF;
    float s, c;
    sincosf(th, &s, &c);

    const int e0 = blockIdx.x * 512 + threadIdx.x;
    const int e1 = e0 + 256;

    // Front-batch all loads for max MLP.
    float4 a0_0, a1_0, b0_0, b1_0;
    float4 a0_1, a1_1, b0_1, b1_1;
    bool p0 = (e0 < n4);
    bool p1 = (e1 < n4);
    if (p0) { a0_0 = r0[e0]; a1_0 = r1[e0]; b0_0 = i0[e0]; b1_0 = i1[e0]; }
    if (p1) { a0_1 = r0[e1]; a1_1 = r1[e1]; b0_1 = i0[e1]; b1_1 = i1[e1]; }

#define ROT(a0, a1, b0, b1, vr0, vr1, vi0, vi1)            \
    do {                                                   \
        vr0.x = fmaf(c, a0.x,  s * b1.x);                  \
        vr0.y = fmaf(c, a0.y,  s * b1.y);                  \
        vr0.z = fmaf(c, a0.z,  s * b1.z);                  \
        vr0.w = fmaf(c, a0.w,  s * b1.w);                  \
        vr1.x = fmaf(c, a1.x,  s * b0.x);                  \
        vr1.y = fmaf(c, a1.y,  s * b0.y);                  \
        vr1.z = fmaf(c, a1.z,  s * b0.z);                  \
        vr1.w = fmaf(c, a1.w,  s * b0.w);                  \
        vi0.x = fmaf(c, b0.x, -s * a1.x);                  \
        vi0.y = fmaf(c, b0.y, -s * a1.y);                  \
        vi0.z = fmaf(c, b0.z, -s * a1.z);                  \
        vi0.w = fmaf(c, b0.w, -s * a1.w);                  \
        vi1.x = fmaf(c, b1.x, -s * a0.x);                  \
        vi1.y = fmaf(c, b1.y, -s * a0.y);                  \
        vi1.z = fmaf(c, b1.z, -s * a0.z);                  \
        vi1.w = fmaf(c, b1.w, -s * a0.w);                  \
    } while (0)

    if (p0) {
        float4 vr0, vr1, vi0, vi1;
        ROT(a0_0, a1_0, b0_0, b1_0, vr0, vr1, vi0, vi1);
        or0[e0] = vr0; or1[e0] = vr1; oi0[e0] = vi0; oi1[e0] = vi1;
    }
    if (p1) {
        float4 vr0, vr1, vi0, vi1;
        ROT(a0_1, a1_1, b0_1, b1_1, vr0, vr1, vi0, vi1);
        or0[e1] = vr0; or1[e1] = vr1; oi0[e1] = vi0; oi1[e1] = vi1;
    }
#undef ROT
}

extern "C" void kernel_launch(void* const* d_in, const int* in_sizes, int n_in,
                              void* d_out, int out_size) {
    const float* amps       = (const float*)d_in[0];   // [20]
    const float* state_real = (const float*)d_in[1];   // [2, B]
    const float* state_imag = (const float*)d_in[2];   // [2, B]
    float* out = (float*)d_out;                        // [2, 2, B]

    const int B  = in_sizes[1] / 2;   // 8388608
    const int n4 = B / 4;             // 2097152 float4 per stream

    const float4* r0 = (const float4*)(state_real);
    const float4* r1 = (const float4*)(state_real + B);
    const float4* i0 = (const float4*)(state_imag);
    const float4* i1 = (const float4*)(state_imag + B);

    float4* or0 = (float4*)(out);
    float4* or1 = (float4*)(out + (size_t)B);
    float4* oi0 = (float4*)(out + 2 * (size_t)B);
    float4* oi1 = (float4*)(out + 3 * (size_t)B);

    int blocks = (n4 + 511) / 512;   // 4096
    grape_fused_kernel<<<blocks, 256>>>(amps, r0, r1, i0, i1,
                                        or0, or1, oi0, oi1, n4);
}

// round 15
// speedup vs baseline: 1.0085x; 1.0078x over previous
#include <cuda_runtime.h>

#define NUM_STEPS 20
#define DT_HALF (0.5f * (1.0f / 20.0f))   // DT/2 = (GATE_TIME/NUM_STEPS)/2

// Champion memory shape (plain LDG.128/STG.128, default policy, 2 float4 per
// stream per thread, front-batched loads) at 512 threads/block: same warp-level
// access pattern, half the CTAs per SM -> lower cross-CTA L1tex-queue spread.
__global__ void __launch_bounds__(512) grape_fused_kernel(
    const float* __restrict__ amps,
    const float4* __restrict__ r0, const float4* __restrict__ r1,
    const float4* __restrict__ i0, const float4* __restrict__ i1,
    float4* __restrict__ or0, float4* __restrict__ or1,
    float4* __restrict__ oi0, float4* __restrict__ oi1,
    int n4)
{
    // Uniform angle: per-thread sum of 20 broadcast loads.
    float th = 0.f;
    #pragma unroll
    for (int k = 0; k < NUM_STEPS; ++k) th += __ldg(&amps[k]);
    th *= DT_HALF;
    float s, c;
    sincosf(th, &s, &c);

    const int e0 = blockIdx.x * 1024 + threadIdx.x;
    const int e1 = e0 + 512;

    // Front-batch all loads for max MLP.
    float4 a0_0, a1_0, b0_0, b1_0;
    float4 a0_1, a1_1, b0_1, b1_1;
    bool p0 = (e0 < n4);
    bool p1 = (e1 < n4);
    if (p0) { a0_0 = r0[e0]; a1_0 = r1[e0]; b0_0 = i0[e0]; b1_0 = i1[e0]; }
    if (p1) { a0_1 = r0[e1]; a1_1 = r1[e1]; b0_1 = i0[e1]; b1_1 = i1[e1]; }

#define ROT(a0, a1, b0, b1, vr0, vr1, vi0, vi1)            \
    do {                                                   \
        vr0.x = fmaf(c, a0.x,  s * b1.x);                  \
        vr0.y = fmaf(c, a0.y,  s * b1.y);                  \
        vr0.z = fmaf(c, a0.z,  s * b1.z);                  \
        vr0.w = fmaf(c, a0.w,  s * b1.w);                  \
        vr1.x = fmaf(c, a1.x,  s * b0.x);                  \
        vr1.y = fmaf(c, a1.y,  s * b0.y);                  \
        vr1.z = fmaf(c, a1.z,  s * b0.z);                  \
        vr1.w = fmaf(c, a1.w,  s * b0.w);                  \
        vi0.x = fmaf(c, b0.x, -s * a1.x);                  \
        vi0.y = fmaf(c, b0.y, -s * a1.y);                  \
        vi0.z = fmaf(c, b0.z, -s * a1.z);                  \
        vi0.w = fmaf(c, b0.w, -s * a1.w);                  \
        vi1.x = fmaf(c, b1.x, -s * a0.x);                  \
        vi1.y = fmaf(c, b1.y, -s * a0.y);                  \
        vi1.z = fmaf(c, b1.z, -s * a0.z);                  \
        vi1.w = fmaf(c, b1.w, -s * a0.w);                  \
    } while (0)

    if (p0) {
        float4 vr0, vr1, vi0, vi1;
        ROT(a0_0, a1_0, b0_0, b1_0, vr0, vr1, vi0, vi1);
        or0[e0] = vr0; or1[e0] = vr1; oi0[e0] = vi0; oi1[e0] = vi1;
    }
    if (p1) {
        float4 vr0, vr1, vi0, vi1;
        ROT(a0_1, a1_1, b0_1, b1_1, vr0, vr1, vi0, vi1);
        or0[e1] = vr0; or1[e1] = vr1; oi0[e1] = vi0; oi1[e1] = vi1;
    }
#undef ROT
}

extern "C" void kernel_launch(void* const* d_in, const int* in_sizes, int n_in,
                              void* d_out, int out_size) {
    const float* amps       = (const float*)d_in[0];   // [20]
    const float* state_real = (const float*)d_in[1];   // [2, B]
    const float* state_imag = (const float*)d_in[2];   // [2, B]
    float* out = (float*)d_out;                        // [2, 2, B]

    const int B  = in_sizes[1] / 2;   // 8388608
    const int n4 = B / 4;             // 2097152 float4 per stream

    const float4* r0 = (const float4*)(state_real);
    const float4* r1 = (const float4*)(state_real + B);
    const float4* i0 = (const float4*)(state_imag);
    const float4* i1 = (const float4*)(state_imag + B);

    float4* or0 = (float4*)(out);
    float4* or1 = (float4*)(out + (size_t)B);
    float4* oi0 = (float4*)(out + 2 * (size_t)B);
    float4* oi1 = (float4*)(out + 3 * (size_t)B);

    int blocks = (n4 + 1023) / 1024;   // 2048
    grape_fused_kernel<<<blocks, 512>>>(amps, r0, r1, i0, i1,
                                        or0, or1, oi0, oi1, n4);
}